// round 5
// baseline (speedup 1.0000x reference)
#include <cuda_runtime.h>
#include <math.h>

#define B_     8
#define N_     10000
#define D_     16
#define E_     320000
#define EH_    32
#define EOUT_  30
#define EOUTP_ 32   // padded agg row (128B-aligned for v4 reductions)
#define NOUT_  64
#define BN_    (B_ * N_)

// ---------------- constant-memory weights ----------------
__constant__ float c_W1[35 * EH_];
__constant__ float c_b1[EH_];
__constant__ float c_Wn[EOUT_ * NOUT_];
__constant__ float c_bn[NOUT_];
__constant__ float c_wind[4];   // wm0, wm1, ws0, ws1

// ---------------- device scratch (no allocations allowed) ----------------
__device__ double g_stats[4];
__device__ float  g_norm[4];                              // mean0, mean1, rstd0, rstd1
__device__ __align__(16) float  g_agg[BN_ * EOUTP_];      // 10.24 MB
__device__ __align__(16) float  g_ys[BN_ * EH_];          // 10.24 MB: b1 + W1s . x
__device__ __align__(16) float  g_yt[BN_ * EH_];          // 10.24 MB: W1t . x
__device__ __align__(8)  float2 g_wind2[BN_];             // (speed, dir) per node

__device__ __forceinline__ float sigmoidf(float v) {
    return 1.0f / (1.0f + __expf(-v));
}

__device__ __forceinline__ void red_v4(float* p, float a, float b, float c, float d) {
    asm volatile("red.global.add.v4.f32 [%0], {%1, %2, %3, %4};"
                 :: "l"(p), "f"(a), "f"(b), "f"(c), "f"(d) : "memory");
}
__device__ __forceinline__ void red_v2(float* p, float a, float b) {
    asm volatile("red.global.add.v2.f32 [%0], {%1, %2};"
                 :: "l"(p), "f"(a), "f"(b) : "memory");
}

// ---------------- zero scratch ----------------
__global__ void zero_kernel() {
    const int total4 = (BN_ * EOUTP_) / 4;
    float4 z = make_float4(0.f, 0.f, 0.f, 0.f);
    for (int i = blockIdx.x * blockDim.x + threadIdx.x; i < total4;
         i += gridDim.x * blockDim.x) {
        ((float4*)g_agg)[i] = z;
    }
    if (blockIdx.x == 0 && threadIdx.x < 4) g_stats[threadIdx.x] = 0.0;
}

// ---------------- edge_attr mean/std (double precision) ----------------
__global__ void stats_kernel(const float* __restrict__ ea) {
    double s0 = 0.0, s1 = 0.0, q0 = 0.0, q1 = 0.0;
    for (int i = blockIdx.x * blockDim.x + threadIdx.x; i < E_;
         i += gridDim.x * blockDim.x) {
        float a = ea[2 * i];
        float b = ea[2 * i + 1];
        s0 += (double)a;
        s1 += (double)b;
        q0 += (double)a * (double)a;
        q1 += (double)b * (double)b;
    }
    for (int o = 16; o > 0; o >>= 1) {
        s0 += __shfl_down_sync(0xffffffffu, s0, o);
        s1 += __shfl_down_sync(0xffffffffu, s1, o);
        q0 += __shfl_down_sync(0xffffffffu, q0, o);
        q1 += __shfl_down_sync(0xffffffffu, q1, o);
    }
    if ((threadIdx.x & 31) == 0) {
        atomicAdd(&g_stats[0], s0);
        atomicAdd(&g_stats[1], s1);
        atomicAdd(&g_stats[2], q0);
        atomicAdd(&g_stats[3], q1);
    }
}

__global__ void finalize_kernel() {
    if (threadIdx.x == 0 && blockIdx.x == 0) {
        const double n = (double)E_;
        double v0 = (g_stats[2] - g_stats[0] * g_stats[0] / n) / (n - 1.0);
        double v1 = (g_stats[3] - g_stats[1] * g_stats[1] / n) / (n - 1.0);
        g_norm[0] = (float)(g_stats[0] / n);
        g_norm[1] = (float)(g_stats[1] / n);
        g_norm[2] = (float)(1.0 / sqrt(v0));
        g_norm[3] = (float)(1.0 / sqrt(v1));
    }
}

// ---------------- per-node projection: ys = b1 + W1s.x, yt = W1t.x, wind ----------
__global__ void __launch_bounds__(128) proj_kernel(const float* __restrict__ x) {
    int node = blockIdx.x * blockDim.x + threadIdx.x;   // flattened (b, n)
    if (node >= BN_) return;

    float xv[D_];
    const float4* px = (const float4*)(x + (size_t)node * D_);
#pragma unroll
    for (int q = 0; q < 4; q++) {
        float4 v = px[q];
        xv[4 * q + 0] = v.x; xv[4 * q + 1] = v.y;
        xv[4 * q + 2] = v.z; xv[4 * q + 3] = v.w;
    }

    float y[EH_];
#pragma unroll
    for (int j = 0; j < EH_; j++) y[j] = c_b1[j];
#pragma unroll
    for (int k = 0; k < D_; k++) {
        float f = xv[k];
#pragma unroll
        for (int j = 0; j < EH_; j++) y[j] = fmaf(f, c_W1[k * EH_ + j], y[j]);
    }
    float4* pys = (float4*)(g_ys + (size_t)node * EH_);
#pragma unroll
    for (int q = 0; q < 8; q++)
        pys[q] = make_float4(y[4 * q], y[4 * q + 1], y[4 * q + 2], y[4 * q + 3]);

#pragma unroll
    for (int j = 0; j < EH_; j++) y[j] = 0.0f;
#pragma unroll
    for (int k = 0; k < D_; k++) {
        float f = xv[k];
#pragma unroll
        for (int j = 0; j < EH_; j++) y[j] = fmaf(f, c_W1[(D_ + k) * EH_ + j], y[j]);
    }
    float4* pyt = (float4*)(g_yt + (size_t)node * EH_);
#pragma unroll
    for (int q = 0; q < 8; q++)
        pyt[q] = make_float4(y[4 * q], y[4 * q + 1], y[4 * q + 2], y[4 * q + 3]);

    g_wind2[node] = make_float2(fmaf(xv[14], c_wind[2], c_wind[0]),
                                fmaf(xv[15], c_wind[3], c_wind[1]));
}

// ---------------- edge kernel: assemble h, layer 2, scatter ----------------
__global__ void __launch_bounds__(256) edge_kernel(
    const int* __restrict__ ei, const float* __restrict__ ea,
    const float* __restrict__ W2, const float* __restrict__ b2)
{
    __shared__ __align__(16) float sW2t[EOUT_ * EH_];   // transposed [30][32]
    __shared__ __align__(16) float sw32[EH_], sw33[EH_], sw34[EH_];
    __shared__ float sb2[EOUT_];

    for (int i = threadIdx.x; i < EH_ * EOUT_; i += blockDim.x) {
        int j = i / EOUT_;
        int o = i % EOUT_;
        sW2t[o * EH_ + j] = W2[i];
    }
    if (threadIdx.x < EH_) {
        sw32[threadIdx.x] = c_W1[32 * EH_ + threadIdx.x];
        sw33[threadIdx.x] = c_W1[33 * EH_ + threadIdx.x];
        sw34[threadIdx.x] = c_W1[34 * EH_ + threadIdx.x];
    }
    if (threadIdx.x < EOUT_) sb2[threadIdx.x] = b2[threadIdx.x];
    __syncthreads();

    unsigned gid = blockIdx.x * blockDim.x + threadIdx.x;
    if (gid >= (unsigned)E_ * B_) return;
    int e = gid >> 3;       // edge id (8 consecutive threads share it)
    int b = gid & 7;        // batch id
    int src = ei[e];
    int tgt = ei[E_ + e];
    int ns = b * N_ + src;
    int nt = b * N_ + tgt;

    float cd   = ea[2 * e];
    float cdi  = ea[2 * e + 1];
    float ean0 = (cd  - g_norm[0]) * g_norm[2];
    float ean1 = (cdi - g_norm[1]) * g_norm[3];
    float2 wd  = g_wind2[ns];
    float theta = fabsf(cdi - wd.y);
    float ewt   = fmaxf(0.0f, 3.0f * wd.x * __cosf(theta) / cd);

    // h = ys[ns] + yt[nt] + ean0*w32 + ean1*w33 + ewt*w34, then sigmoid
    float h[EH_];
    const float4* pys = (const float4*)(g_ys + (size_t)ns * EH_);
    const float4* pyt = (const float4*)(g_yt + (size_t)nt * EH_);
#pragma unroll
    for (int q = 0; q < 8; q++) {
        float4 a = pys[q];
        float4 c = pyt[q];
        float4 v0 = ((const float4*)sw32)[q];
        float4 v1 = ((const float4*)sw33)[q];
        float4 v2 = ((const float4*)sw34)[q];
        h[4 * q + 0] = sigmoidf(a.x + c.x + fmaf(ean0, v0.x, fmaf(ean1, v1.x, ewt * v2.x)));
        h[4 * q + 1] = sigmoidf(a.y + c.y + fmaf(ean0, v0.y, fmaf(ean1, v1.y, ewt * v2.y)));
        h[4 * q + 2] = sigmoidf(a.z + c.z + fmaf(ean0, v0.z, fmaf(ean1, v1.z, ewt * v2.z)));
        h[4 * q + 3] = sigmoidf(a.w + c.w + fmaf(ean0, v0.w, fmaf(ean1, v1.w, ewt * v2.w)));
    }

    // layer 2 + scatter, 4 outputs at a time
    float* at = g_agg + (size_t)nt * EOUTP_;
    float* as = g_agg + (size_t)ns * EOUTP_;

#pragma unroll
    for (int c4 = 0; c4 < 7; c4++) {
        int o0 = 4 * c4;
        float a0 = sb2[o0 + 0], a1 = sb2[o0 + 1], a2 = sb2[o0 + 2], a3 = sb2[o0 + 3];
#pragma unroll
        for (int jj = 0; jj < 8; jj++) {
            float4 w0 = ((const float4*)(sW2t + (o0 + 0) * EH_))[jj];
            float4 w1 = ((const float4*)(sW2t + (o0 + 1) * EH_))[jj];
            float4 w2 = ((const float4*)(sW2t + (o0 + 2) * EH_))[jj];
            float4 w3 = ((const float4*)(sW2t + (o0 + 3) * EH_))[jj];
            float h0 = h[4 * jj + 0], h1 = h[4 * jj + 1];
            float h2 = h[4 * jj + 2], h3 = h[4 * jj + 3];
            a0 = fmaf(h0, w0.x, a0); a0 = fmaf(h1, w0.y, a0);
            a0 = fmaf(h2, w0.z, a0); a0 = fmaf(h3, w0.w, a0);
            a1 = fmaf(h0, w1.x, a1); a1 = fmaf(h1, w1.y, a1);
            a1 = fmaf(h2, w1.z, a1); a1 = fmaf(h3, w1.w, a1);
            a2 = fmaf(h0, w2.x, a2); a2 = fmaf(h1, w2.y, a2);
            a2 = fmaf(h2, w2.z, a2); a2 = fmaf(h3, w2.w, a2);
            a3 = fmaf(h0, w3.x, a3); a3 = fmaf(h1, w3.y, a3);
            a3 = fmaf(h2, w3.z, a3); a3 = fmaf(h3, w3.w, a3);
        }
        float e0 = sigmoidf(a0), e1 = sigmoidf(a1);
        float e2 = sigmoidf(a2), e3 = sigmoidf(a3);
        red_v4(at + o0,  e0,  e1,  e2,  e3);
        red_v4(as + o0, -e0, -e1, -e2, -e3);
    }
    {
        float a0 = sb2[28], a1 = sb2[29];
#pragma unroll
        for (int jj = 0; jj < 8; jj++) {
            float4 w0 = ((const float4*)(sW2t + 28 * EH_))[jj];
            float4 w1 = ((const float4*)(sW2t + 29 * EH_))[jj];
            float h0 = h[4 * jj + 0], h1 = h[4 * jj + 1];
            float h2 = h[4 * jj + 2], h3 = h[4 * jj + 3];
            a0 = fmaf(h0, w0.x, a0); a0 = fmaf(h1, w0.y, a0);
            a0 = fmaf(h2, w0.z, a0); a0 = fmaf(h3, w0.w, a0);
            a1 = fmaf(h0, w1.x, a1); a1 = fmaf(h1, w1.y, a1);
            a1 = fmaf(h2, w1.z, a1); a1 = fmaf(h3, w1.w, a1);
        }
        float e0 = sigmoidf(a0), e1 = sigmoidf(a1);
        red_v2(at + 28,  e0,  e1);
        red_v2(as + 28, -e0, -e1);
    }
}

// ---------------- node MLP (constant weights) ----------------
__global__ void __launch_bounds__(256) node_kernel(float* __restrict__ out)
{
    int node = blockIdx.x * blockDim.x + threadIdx.x;
    if (node >= BN_) return;

    float a[EOUT_];
    const float4* ag = (const float4*)(g_agg + (size_t)node * EOUTP_);
#pragma unroll
    for (int q = 0; q < 7; q++) {
        float4 v = ag[q];
        a[4 * q + 0] = v.x; a[4 * q + 1] = v.y;
        a[4 * q + 2] = v.z; a[4 * q + 3] = v.w;
    }
    {
        float4 v = ag[7];
        a[28] = v.x; a[29] = v.y;
    }

    float* op = out + (size_t)node * NOUT_;
#pragma unroll
    for (int o = 0; o < NOUT_; o += 8) {
        float acc[8];
#pragma unroll
        for (int t = 0; t < 8; t++) acc[t] = c_bn[o + t];
#pragma unroll
        for (int j = 0; j < EOUT_; j++) {
            float aj = a[j];
#pragma unroll
            for (int t = 0; t < 8; t++)
                acc[t] = fmaf(aj, c_Wn[j * NOUT_ + o + t], acc[t]);
        }
        float4 r0 = make_float4(sigmoidf(acc[0]), sigmoidf(acc[1]),
                                sigmoidf(acc[2]), sigmoidf(acc[3]));
        float4 r1 = make_float4(sigmoidf(acc[4]), sigmoidf(acc[5]),
                                sigmoidf(acc[6]), sigmoidf(acc[7]));
        *(float4*)(op + o)     = r0;
        *(float4*)(op + o + 4) = r1;
    }
}

// ---------------- launch ----------------
extern "C" void kernel_launch(void* const* d_in, const int* in_sizes, int n_in,
                              void* d_out, int out_size) {
    const float* x  = (const float*)d_in[0];
    const int*   ei = (const int*)d_in[1];
    const float* ea = (const float*)d_in[2];
    const float* wm = (const float*)d_in[3];
    const float* ws = (const float*)d_in[4];
    const float* W1 = (const float*)d_in[5];
    const float* b1 = (const float*)d_in[6];
    const float* W2 = (const float*)d_in[7];
    const float* b2 = (const float*)d_in[8];
    const float* Wn = (const float*)d_in[9];
    const float* bn = (const float*)d_in[10];
    float* out = (float*)d_out;

    cudaMemcpyToSymbolAsync(c_W1, W1, 35 * EH_ * sizeof(float), 0,
                            cudaMemcpyDeviceToDevice, 0);
    cudaMemcpyToSymbolAsync(c_b1, b1, EH_ * sizeof(float), 0,
                            cudaMemcpyDeviceToDevice, 0);
    cudaMemcpyToSymbolAsync(c_Wn, Wn, EOUT_ * NOUT_ * sizeof(float), 0,
                            cudaMemcpyDeviceToDevice, 0);
    cudaMemcpyToSymbolAsync(c_bn, bn, NOUT_ * sizeof(float), 0,
                            cudaMemcpyDeviceToDevice, 0);
    cudaMemcpyToSymbolAsync(c_wind, wm, 2 * sizeof(float), 0,
                            cudaMemcpyDeviceToDevice, 0);
    cudaMemcpyToSymbolAsync(c_wind, ws, 2 * sizeof(float), 2 * sizeof(float),
                            cudaMemcpyDeviceToDevice, 0);

    zero_kernel<<<512, 256>>>();
    stats_kernel<<<256, 256>>>(ea);
    finalize_kernel<<<1, 32>>>();
    proj_kernel<<<(BN_ + 127) / 128, 128>>>(x);
    edge_kernel<<<(E_ * B_) / 256, 256>>>(ei, ea, W2, b2);
    node_kernel<<<(BN_ + 255) / 256, 256>>>(out);
}

// round 6
// speedup vs baseline: 1.1406x; 1.1406x over previous
#include <cuda_runtime.h>
#include <math.h>

#define B_     8
#define N_     10000
#define D_     16
#define E_     320000
#define EH_    32
#define EOUT_  30
#define EOUTP_ 32   // padded agg row (128B-aligned for v4 reductions)
#define NOUT_  64
#define BN_    (B_ * N_)

typedef unsigned long long ull;

// ---------------- constant-memory weights ----------------
__constant__ float c_W1[35 * EH_];
__constant__ float c_b1[EH_];
__constant__ float c_Wn[EOUT_ * NOUT_];
__constant__ float c_bn[NOUT_];
__constant__ float c_wind[4];   // wm0, wm1, ws0, ws1

// ---------------- device scratch ----------------
__device__ double g_stats[4];
__device__ float  g_norm[4];
__device__ __align__(16) float g_agg[BN_ * EOUTP_];

__device__ __forceinline__ float sigmoidf(float v) {
    return 1.0f / (1.0f + __expf(-v));
}

__device__ __forceinline__ ull pack_f2(float lo, float hi) {
    ull r;
    asm("mov.b64 %0, {%1, %2};" : "=l"(r) : "f"(lo), "f"(hi));
    return r;
}
__device__ __forceinline__ void unpack_f2(ull v, float& lo, float& hi) {
    asm("mov.b64 {%0, %1}, %2;" : "=f"(lo), "=f"(hi) : "l"(v));
}
__device__ __forceinline__ ull fma_f2(ull a, ull b, ull c) {
    ull d;
    asm("fma.rn.f32x2 %0, %1, %2, %3;" : "=l"(d) : "l"(a), "l"(b), "l"(c));
    return d;
}

__device__ __forceinline__ void red_v4(float* p, float a, float b, float c, float d) {
    asm volatile("red.global.add.v4.f32 [%0], {%1, %2, %3, %4};"
                 :: "l"(p), "f"(a), "f"(b), "f"(c), "f"(d) : "memory");
}
__device__ __forceinline__ void red_v2(float* p, float a, float b) {
    asm volatile("red.global.add.v2.f32 [%0], {%1, %2};"
                 :: "l"(p), "f"(a), "f"(b) : "memory");
}

// ---------------- zero scratch ----------------
__global__ void zero_kernel() {
    const int total4 = (BN_ * EOUTP_) / 4;
    float4 z = make_float4(0.f, 0.f, 0.f, 0.f);
    for (int i = blockIdx.x * blockDim.x + threadIdx.x; i < total4;
         i += gridDim.x * blockDim.x) {
        ((float4*)g_agg)[i] = z;
    }
    if (blockIdx.x == 0 && threadIdx.x < 4) g_stats[threadIdx.x] = 0.0;
}

// ---------------- edge_attr mean/std (double precision) ----------------
__global__ void stats_kernel(const float* __restrict__ ea) {
    double s0 = 0.0, s1 = 0.0, q0 = 0.0, q1 = 0.0;
    for (int i = blockIdx.x * blockDim.x + threadIdx.x; i < E_;
         i += gridDim.x * blockDim.x) {
        float a = ea[2 * i];
        float b = ea[2 * i + 1];
        s0 += (double)a;
        s1 += (double)b;
        q0 += (double)a * (double)a;
        q1 += (double)b * (double)b;
    }
    for (int o = 16; o > 0; o >>= 1) {
        s0 += __shfl_down_sync(0xffffffffu, s0, o);
        s1 += __shfl_down_sync(0xffffffffu, s1, o);
        q0 += __shfl_down_sync(0xffffffffu, q0, o);
        q1 += __shfl_down_sync(0xffffffffu, q1, o);
    }
    if ((threadIdx.x & 31) == 0) {
        atomicAdd(&g_stats[0], s0);
        atomicAdd(&g_stats[1], s1);
        atomicAdd(&g_stats[2], q0);
        atomicAdd(&g_stats[3], q1);
    }
}

__global__ void finalize_kernel() {
    if (threadIdx.x == 0 && blockIdx.x == 0) {
        const double n = (double)E_;
        double v0 = (g_stats[2] - g_stats[0] * g_stats[0] / n) / (n - 1.0);
        double v1 = (g_stats[3] - g_stats[1] * g_stats[1] / n) / (n - 1.0);
        g_norm[0] = (float)(g_stats[0] / n);
        g_norm[1] = (float)(g_stats[1] / n);
        g_norm[2] = (float)(1.0 / sqrt(v0));
        g_norm[3] = (float)(1.0 / sqrt(v1));
    }
}

// ---------------- edge MLP + scatter (f32x2 math) ----------
__global__ void __launch_bounds__(256) edge_kernel(
    const float* __restrict__ x, const int* __restrict__ ei,
    const float* __restrict__ ea,
    const float* __restrict__ W2, const float* __restrict__ b2)
{
    // transposed layer-2 weights in shared (broadcast LDS, off the constant port)
    __shared__ __align__(16) float sW2t[EOUT_ * EH_];   // [30][32]
    __shared__ float sb2[EOUT_];
    for (int i = threadIdx.x; i < EH_ * EOUT_; i += blockDim.x) {
        int j = i / EOUT_;
        int o = i % EOUT_;
        sW2t[o * EH_ + j] = W2[i];
    }
    if (threadIdx.x < EOUT_) sb2[threadIdx.x] = b2[threadIdx.x];
    __syncthreads();

    unsigned gid = blockIdx.x * blockDim.x + threadIdx.x;
    if (gid >= (unsigned)(E_) * B_) return;
    int e = gid >> 3;       // edge id
    int b = gid & 7;        // batch id
    int src = ei[e];
    int tgt = ei[E_ + e];

    float xs[D_], xt[D_];
    const float4* ps = (const float4*)(x + (size_t)(b * N_ + src) * D_);
    const float4* pt = (const float4*)(x + (size_t)(b * N_ + tgt) * D_);
#pragma unroll
    for (int q = 0; q < 4; q++) {
        float4 v = ps[q];
        xs[4 * q + 0] = v.x; xs[4 * q + 1] = v.y;
        xs[4 * q + 2] = v.z; xs[4 * q + 3] = v.w;
        float4 w = pt[q];
        xt[4 * q + 0] = w.x; xt[4 * q + 1] = w.y;
        xt[4 * q + 2] = w.z; xt[4 * q + 3] = w.w;
    }

    float speed = fmaf(xs[14], c_wind[2], c_wind[0]);
    float dir   = fmaf(xs[15], c_wind[3], c_wind[1]);
    float cd    = ea[2 * e];
    float cdi   = ea[2 * e + 1];
    float theta = fabsf(cdi - dir);
    float ewt   = fmaxf(0.0f, 3.0f * speed * __cosf(theta) / cd);
    float ean0  = (cd  - g_norm[0]) * g_norm[2];
    float ean1  = (cdi - g_norm[1]) * g_norm[3];

    // ---- layer 1 in f32x2: h2[q] holds hidden pair (2q, 2q+1) ----
    ull h2[16];
    {
        const ulonglong2* pb = (const ulonglong2*)c_b1;
#pragma unroll
        for (int q = 0; q < 8; q++) {
            ulonglong2 v = pb[q];
            h2[2 * q]     = v.x;
            h2[2 * q + 1] = v.y;
        }
    }

#pragma unroll
    for (int k = 0; k < D_; k++) {
        ull f2 = pack_f2(xs[k], xs[k]);
        const ulonglong2* w = (const ulonglong2*)(c_W1 + k * EH_);
#pragma unroll
        for (int q = 0; q < 8; q++) {
            ulonglong2 wv = w[q];
            h2[2 * q]     = fma_f2(f2, wv.x, h2[2 * q]);
            h2[2 * q + 1] = fma_f2(f2, wv.y, h2[2 * q + 1]);
        }
    }
#pragma unroll
    for (int k = 0; k < D_; k++) {
        ull f2 = pack_f2(xt[k], xt[k]);
        const ulonglong2* w = (const ulonglong2*)(c_W1 + (D_ + k) * EH_);
#pragma unroll
        for (int q = 0; q < 8; q++) {
            ulonglong2 wv = w[q];
            h2[2 * q]     = fma_f2(f2, wv.x, h2[2 * q]);
            h2[2 * q + 1] = fma_f2(f2, wv.y, h2[2 * q + 1]);
        }
    }
    {
        ull e02 = pack_f2(ean0, ean0);
        ull e12 = pack_f2(ean1, ean1);
        ull ew2 = pack_f2(ewt,  ewt);
        const ulonglong2* w32 = (const ulonglong2*)(c_W1 + 32 * EH_);
        const ulonglong2* w33 = (const ulonglong2*)(c_W1 + 33 * EH_);
        const ulonglong2* w34 = (const ulonglong2*)(c_W1 + 34 * EH_);
#pragma unroll
        for (int q = 0; q < 8; q++) {
            ulonglong2 v0 = w32[q];
            ulonglong2 v1 = w33[q];
            ulonglong2 v2 = w34[q];
            h2[2 * q]     = fma_f2(e02, v0.x, h2[2 * q]);
            h2[2 * q + 1] = fma_f2(e02, v0.y, h2[2 * q + 1]);
            h2[2 * q]     = fma_f2(e12, v1.x, h2[2 * q]);
            h2[2 * q + 1] = fma_f2(e12, v1.y, h2[2 * q + 1]);
            h2[2 * q]     = fma_f2(ew2, v2.x, h2[2 * q]);
            h2[2 * q + 1] = fma_f2(ew2, v2.y, h2[2 * q + 1]);
        }
    }

    // sigmoid, repack
#pragma unroll
    for (int i = 0; i < 16; i++) {
        float lo, hi;
        unpack_f2(h2[i], lo, hi);
        h2[i] = pack_f2(sigmoidf(lo), sigmoidf(hi));
    }

    // ---- layer 2 (paired accumulate) + scatter ----
    float* at = g_agg + (size_t)(b * N_ + tgt) * EOUTP_;
    float* as = g_agg + (size_t)(b * N_ + src) * EOUTP_;

    float ev[EOUT_];
#pragma unroll
    for (int o = 0; o < EOUT_; o++) {
        ull acc2 = pack_f2(sb2[o], 0.0f);
        const ulonglong2* w = (const ulonglong2*)(sW2t + o * EH_);
#pragma unroll
        for (int q = 0; q < 8; q++) {
            ulonglong2 wv = w[q];
            acc2 = fma_f2(h2[2 * q],     wv.x, acc2);
            acc2 = fma_f2(h2[2 * q + 1], wv.y, acc2);
        }
        float lo, hi;
        unpack_f2(acc2, lo, hi);
        ev[o] = sigmoidf(lo + hi);
    }

#pragma unroll
    for (int c4 = 0; c4 < 7; c4++) {
        int o0 = 4 * c4;
        red_v4(at + o0,  ev[o0 + 0],  ev[o0 + 1],  ev[o0 + 2],  ev[o0 + 3]);
        red_v4(as + o0, -ev[o0 + 0], -ev[o0 + 1], -ev[o0 + 2], -ev[o0 + 3]);
    }
    red_v2(at + 28,  ev[28],  ev[29]);
    red_v2(as + 28, -ev[28], -ev[29]);
}

// ---------------- node MLP (constant weights) ----------------
__global__ void __launch_bounds__(256) node_kernel(float* __restrict__ out)
{
    int node = blockIdx.x * blockDim.x + threadIdx.x;
    if (node >= BN_) return;

    float a[EOUT_];
    const float4* ag = (const float4*)(g_agg + (size_t)node * EOUTP_);
#pragma unroll
    for (int q = 0; q < 7; q++) {
        float4 v = ag[q];
        a[4 * q + 0] = v.x; a[4 * q + 1] = v.y;
        a[4 * q + 2] = v.z; a[4 * q + 3] = v.w;
    }
    {
        float4 v = ag[7];
        a[28] = v.x; a[29] = v.y;
    }

    float* op = out + (size_t)node * NOUT_;
#pragma unroll
    for (int o = 0; o < NOUT_; o += 8) {
        float acc[8];
#pragma unroll
        for (int t = 0; t < 8; t++) acc[t] = c_bn[o + t];
#pragma unroll
        for (int j = 0; j < EOUT_; j++) {
            float aj = a[j];
#pragma unroll
            for (int t = 0; t < 8; t++)
                acc[t] = fmaf(aj, c_Wn[j * NOUT_ + o + t], acc[t]);
        }
        float4 r0 = make_float4(sigmoidf(acc[0]), sigmoidf(acc[1]),
                                sigmoidf(acc[2]), sigmoidf(acc[3]));
        float4 r1 = make_float4(sigmoidf(acc[4]), sigmoidf(acc[5]),
                                sigmoidf(acc[6]), sigmoidf(acc[7]));
        *(float4*)(op + o)     = r0;
        *(float4*)(op + o + 4) = r1;
    }
}

// ---------------- launch ----------------
extern "C" void kernel_launch(void* const* d_in, const int* in_sizes, int n_in,
                              void* d_out, int out_size) {
    const float* x  = (const float*)d_in[0];
    const int*   ei = (const int*)d_in[1];
    const float* ea = (const float*)d_in[2];
    const float* wm = (const float*)d_in[3];
    const float* ws = (const float*)d_in[4];
    const float* W1 = (const float*)d_in[5];
    const float* b1 = (const float*)d_in[6];
    const float* W2 = (const float*)d_in[7];
    const float* b2 = (const float*)d_in[8];
    const float* Wn = (const float*)d_in[9];
    const float* bn = (const float*)d_in[10];
    float* out = (float*)d_out;

    cudaMemcpyToSymbolAsync(c_W1, W1, 35 * EH_ * sizeof(float), 0,
                            cudaMemcpyDeviceToDevice, 0);
    cudaMemcpyToSymbolAsync(c_b1, b1, EH_ * sizeof(float), 0,
                            cudaMemcpyDeviceToDevice, 0);
    cudaMemcpyToSymbolAsync(c_Wn, Wn, EOUT_ * NOUT_ * sizeof(float), 0,
                            cudaMemcpyDeviceToDevice, 0);
    cudaMemcpyToSymbolAsync(c_bn, bn, NOUT_ * sizeof(float), 0,
                            cudaMemcpyDeviceToDevice, 0);
    cudaMemcpyToSymbolAsync(c_wind, wm, 2 * sizeof(float), 0,
                            cudaMemcpyDeviceToDevice, 0);
    cudaMemcpyToSymbolAsync(c_wind, ws, 2 * sizeof(float), 2 * sizeof(float),
                            cudaMemcpyDeviceToDevice, 0);

    zero_kernel<<<512, 256>>>();
    stats_kernel<<<256, 256>>>(ea);
    finalize_kernel<<<1, 32>>>();
    edge_kernel<<<(E_ * B_) / 256, 256>>>(x, ei, ea, W2, b2);
    node_kernel<<<(BN_ + 255) / 256, 256>>>(out);
}